// round 1
// baseline (speedup 1.0000x reference)
#include <cuda_runtime.h>
#include <math.h>

// ---------------------------------------------------------------------------
// GaussianRasterizer: tile-based 2D Gaussian splatting.
// Inputs (metadata order): opacity[N], means[N,2], stds[N,2], rhos[N],
//   colors[N,3], image_height, image_width, scale_factor, raster_ratio.
// Output: [H, W, 3] float32.
// ---------------------------------------------------------------------------

#define MAXN 8192
#define TILE 16
#define CHUNK 256

// Per-Gaussian precomputed parameters (scratch via __device__ globals —
// no allocation allowed in kernel_launch).
__device__ float g_xlo[MAXN], g_xhi[MAXN], g_ylo[MAXN], g_yhi[MAXN];
__device__ float g_mx[MAXN],  g_my[MAXN];
__device__ float g_ia[MAXN],  g_ib2[MAXN], g_ic[MAXN];
__device__ float g_cr[MAXN],  g_cg[MAXN],  g_cb[MAXN];
__device__ float g_cut2;

// Scalars may arrive as int32 or float32 bits; small-int values are
// unambiguous (1 as float bits would be a huge int), so disambiguate.
__device__ __forceinline__ float scalar_as_float(const int* p) {
    int v = *p;
    if (v >= 0 && v <= 1000000) return (float)v;
    return __int_as_float(v);
}

__global__ void gr_prepass(const float* __restrict__ opacity,
                           const float* __restrict__ means,
                           const float* __restrict__ stds,
                           const float* __restrict__ rhos,
                           const float* __restrict__ colors,
                           const int*   __restrict__ scale_p,
                           const int*   __restrict__ ratio_p,
                           int N) {
    int i = blockIdx.x * blockDim.x + threadIdx.x;
    float r = scalar_as_float(ratio_p);
    if (i == 0) g_cut2 = r * r;
    if (i >= N) return;

    float s   = scalar_as_float(scale_p);
    float sx  = stds[2 * i + 0] * s;
    float sy  = stds[2 * i + 1] * s;
    float rho = rhos[i];
    float om  = 1.0f - rho * rho;

    float ia = 1.0f / (sx * sx * om);
    float ic = 1.0f / (sy * sy * om);
    float ib = -rho / (sx * sy * om);

    float mx = means[2 * i + 0];
    float my = means[2 * i + 1];

    g_mx[i]  = mx;
    g_my[i]  = my;
    g_ia[i]  = ia;
    g_ib2[i] = 2.0f * ib;
    g_ic[i]  = ic;

    // Exact cull bound: min_dy mahal2(dx, dy) = dx^2 / sx^2, so pixels with
    // |dx| > r*sx are guaranteed mahal2 > r^2 (and symmetrically in y).
    g_xlo[i] = mx - r * sx;
    g_xhi[i] = mx + r * sx;
    g_ylo[i] = my - r * sy;
    g_yhi[i] = my + r * sy;

    float o = opacity[i];
    g_cr[i] = o * colors[3 * i + 0];
    g_cg[i] = o * colors[3 * i + 1];
    g_cb[i] = o * colors[3 * i + 2];
}

__global__ __launch_bounds__(256)
void gr_raster(float* __restrict__ out, int N, int W, int H) {
    // Compacted Gaussian SoA for the current chunk:
    // [0]=mx [1]=my [2]=ia [3]=ib2 [4]=ic [5]=cr [6]=cg [7]=cb
    __shared__ float sp[8][CHUNK];
    __shared__ int   swc[8];

    const int tid  = threadIdx.x;
    const int lane = tid & 31;
    const int wid  = tid >> 5;
    const int tx   = tid & (TILE - 1);
    const int ty   = tid >> 4;

    const int px = blockIdx.x * TILE + tx;
    const int py = blockIdx.y * TILE + ty;
    const float x = (float)px + 0.5f;
    const float y = (float)py + 0.5f;

    // Tile bounds in pixel-center coordinates.
    const float tX0 = (float)(blockIdx.x * TILE) + 0.5f;
    const float tX1 = tX0 + (float)(TILE - 1);
    const float tY0 = (float)(blockIdx.y * TILE) + 0.5f;
    const float tY1 = tY0 + (float)(TILE - 1);

    const float cut2 = g_cut2;

    float ar = 0.0f, ag = 0.0f, ab = 0.0f;

    for (int base = 0; base < N; base += CHUNK) {
        const int i = base + tid;
        bool hit = false;
        if (i < N) {
            float xlo = g_xlo[i], xhi = g_xhi[i];
            float ylo = g_ylo[i], yhi = g_yhi[i];
            hit = (xlo <= tX1) & (xhi >= tX0) & (ylo <= tY1) & (yhi >= tY0);
        }

        // Deterministic compaction: warp ballot + cross-warp prefix.
        unsigned m = __ballot_sync(0xffffffffu, hit);
        if (lane == 0) swc[wid] = __popc(m);
        __syncthreads();   // S1: swc ready; also: all threads done with prev eval

        int off = 0, total = 0;
        #pragma unroll
        for (int w = 0; w < 8; w++) {
            int c = swc[w];
            if (w < wid) off += c;
            total += c;
        }

        if (hit) {
            int slot = off + __popc(m & ((1u << lane) - 1u));
            sp[0][slot] = g_mx[i];
            sp[1][slot] = g_my[i];
            sp[2][slot] = g_ia[i];
            sp[3][slot] = g_ib2[i];
            sp[4][slot] = g_ic[i];
            sp[5][slot] = g_cr[i];
            sp[6][slot] = g_cg[i];
            sp[7][slot] = g_cb[i];
        }
        __syncthreads();   // S2: sp populated

        // Evaluate this pixel against all surviving Gaussians (smem broadcast).
        for (int j = 0; j < total; j++) {
            float dx  = x - sp[0][j];
            float dy  = y - sp[1][j];
            float m2  = sp[2][j] * dx * dx;
            m2 = fmaf(sp[3][j] * dx, dy, m2);
            m2 = fmaf(sp[4][j] * dy, dy, m2);
            if (m2 <= cut2) {
                float wgt = __expf(-0.5f * m2);
                ar = fmaf(wgt, sp[5][j], ar);
                ag = fmaf(wgt, sp[6][j], ag);
                ab = fmaf(wgt, sp[7][j], ab);
            }
        }
    }

    if (px < W && py < H) {
        int o = (py * W + px) * 3;
        out[o + 0] = ar;
        out[o + 1] = ag;
        out[o + 2] = ab;
    }
}

extern "C" void kernel_launch(void* const* d_in, const int* in_sizes, int n_in,
                              void* d_out, int out_size) {
    const float* opacity = (const float*)d_in[0];
    const float* means   = (const float*)d_in[1];
    const float* stds    = (const float*)d_in[2];
    const float* rhos    = (const float*)d_in[3];
    const float* colors  = (const float*)d_in[4];
    const int*   scale_p = (const int*)d_in[7];
    const int*   ratio_p = (const int*)d_in[8];

    int N = in_sizes[0];
    if (N > MAXN) N = MAXN;

    // Derive H, W host-side from out_size (H*W*3); assume square raster
    // (setup uses H == W). Graph capture forbids reading device scalars here.
    int hw = out_size / 3;
    int W = (int)lrint(sqrt((double)hw));
    while (W > 1 && (hw % W) != 0) W--;
    int H = hw / W;

    float* out = (float*)d_out;

    gr_prepass<<<(N + 255) / 256, 256>>>(opacity, means, stds, rhos, colors,
                                         scale_p, ratio_p, N);

    dim3 grid((W + TILE - 1) / TILE, (H + TILE - 1) / TILE);
    gr_raster<<<grid, 256>>>(out, N, W, H);
}

// round 2
// speedup vs baseline: 1.0152x; 1.0152x over previous
#include <cuda_runtime.h>
#include <math.h>

// ---------------------------------------------------------------------------
// GaussianRasterizer: tile-based 2D Gaussian splatting (float4 / scan version)
// Inputs: opacity[N], means[N,2], stds[N,2], rhos[N], colors[N,3],
//         image_height, image_width, scale_factor, raster_ratio.
// Output: [H, W, 3] float32.
// ---------------------------------------------------------------------------

#define MAXN 8192
#define TILE_W 16
#define TILE_H 8
#define NTHREADS 128
#define NWARPS (NTHREADS / 32)
#define CPT 4                       // candidates per thread per chunk
#define CHUNK (NTHREADS * CPT)      // 512

// Per-Gaussian precomputed parameters (__device__ globals = legal scratch).
__device__ float4 g_bbox[MAXN];     // xlo, ylo, xhi, yhi
__device__ float4 g_p0[MAXN];       // mx, my, ia, ib2
__device__ float4 g_p1[MAXN];       // ic, cr, cg, cb
__device__ float  g_cut2;

// Scalars may arrive as int32 or float32 bits; small ints are unambiguous.
__device__ __forceinline__ float scalar_as_float(const int* p) {
    int v = *p;
    if (v >= 0 && v <= 1000000) return (float)v;
    return __int_as_float(v);
}

__global__ void gr_prepass(const float* __restrict__ opacity,
                           const float* __restrict__ means,
                           const float* __restrict__ stds,
                           const float* __restrict__ rhos,
                           const float* __restrict__ colors,
                           const int*   __restrict__ scale_p,
                           const int*   __restrict__ ratio_p,
                           int N) {
    int i = blockIdx.x * blockDim.x + threadIdx.x;
    float r = scalar_as_float(ratio_p);
    if (i == 0) g_cut2 = r * r;
    if (i >= N) return;

    float s   = scalar_as_float(scale_p);
    float sx  = stds[2 * i + 0] * s;
    float sy  = stds[2 * i + 1] * s;
    float rho = rhos[i];
    float om  = 1.0f - rho * rho;

    float ia = 1.0f / (sx * sx * om);
    float ic = 1.0f / (sy * sy * om);
    float ib = -rho / (sx * sy * om);

    float mx = means[2 * i + 0];
    float my = means[2 * i + 1];

    // Exact cull: min over dy of mahal2 at fixed dx is dx^2/sx^2, so
    // |dx| > r*sx  =>  mahal2 > r^2 (symmetrically in y).
    g_bbox[i] = make_float4(mx - r * sx, my - r * sy, mx + r * sx, my + r * sy);
    g_p0[i]   = make_float4(mx, my, ia, 2.0f * ib);

    float o = opacity[i];
    g_p1[i] = make_float4(ic, o * colors[3 * i + 0],
                              o * colors[3 * i + 1],
                              o * colors[3 * i + 2]);
}

__global__ __launch_bounds__(NTHREADS)
void gr_raster(float* __restrict__ out, int N, int W, int H) {
    __shared__ float4 s0[CHUNK];
    __shared__ float4 s1[CHUNK];
    __shared__ int    swc[NWARPS];

    const int tid  = threadIdx.x;
    const int lane = tid & 31;
    const int wid  = tid >> 5;

    const int px = blockIdx.x * TILE_W + (tid & (TILE_W - 1));
    const int py = blockIdx.y * TILE_H + (tid / TILE_W);
    const float x = (float)px + 0.5f;
    const float y = (float)py + 0.5f;

    // Tile bounds in pixel-center coords.
    const float tX0 = (float)(blockIdx.x * TILE_W) + 0.5f;
    const float tX1 = tX0 + (float)(TILE_W - 1);
    const float tY0 = (float)(blockIdx.y * TILE_H) + 0.5f;
    const float tY1 = tY0 + (float)(TILE_H - 1);

    const float cut2 = g_cut2;

    float ar0 = 0.0f, ag0 = 0.0f, ab0 = 0.0f;
    float ar1 = 0.0f, ag1 = 0.0f, ab1 = 0.0f;

    for (int base = 0; base < N; base += CHUNK) {
        // ---- Cull: 4 contiguous candidates per thread (front-batched LDGs)
        const int ibase = base + tid * CPT;
        unsigned hm = 0;
        int cnt = 0;
        #pragma unroll
        for (int k = 0; k < CPT; k++) {
            int i = ibase + k;
            if (i < N) {
                float4 bb = g_bbox[i];
                bool hit = (bb.x <= tX1) & (bb.z >= tX0) &
                           (bb.y <= tY1) & (bb.w >= tY0);
                if (hit) { hm |= (1u << k); cnt++; }
            }
        }

        // ---- Deterministic block-level exclusive scan of cnt
        int incl = cnt;
        #pragma unroll
        for (int d = 1; d < 32; d <<= 1) {
            int v = __shfl_up_sync(0xffffffffu, incl, d);
            if (lane >= d) incl += v;
        }
        if (lane == 31) swc[wid] = incl;
        __syncthreads();                 // also: all evals of prev chunk done

        int blockoff = 0, total = 0;
        #pragma unroll
        for (int w = 0; w < NWARPS; w++) {
            int c = swc[w];
            if (w < wid) blockoff += c;
            total += c;
        }
        int slot = blockoff + (incl - cnt);

        #pragma unroll
        for (int k = 0; k < CPT; k++) {
            if ((hm >> k) & 1u) {
                int i = ibase + k;
                s0[slot] = g_p0[i];
                s1[slot] = g_p1[i];
                slot++;
            }
        }
        __syncthreads();                 // survivor list ready

        // ---- Eval: 2-way unrolled, dual accumulators
        int j = 0;
        for (; j + 1 < total; j += 2) {
            float4 a0 = s0[j],     b0 = s1[j];
            float4 a1 = s0[j + 1], b1 = s1[j + 1];

            float dx0 = x - a0.x, dy0 = y - a0.y;
            float m20 = a0.z * dx0 * dx0;
            m20 = fmaf(a0.w * dx0, dy0, m20);
            m20 = fmaf(b0.x * dy0, dy0, m20);

            float dx1 = x - a1.x, dy1 = y - a1.y;
            float m21 = a1.z * dx1 * dx1;
            m21 = fmaf(a1.w * dx1, dy1, m21);
            m21 = fmaf(b1.x * dy1, dy1, m21);

            if (m20 <= cut2) {
                float w0 = __expf(-0.5f * m20);
                ar0 = fmaf(w0, b0.y, ar0);
                ag0 = fmaf(w0, b0.z, ag0);
                ab0 = fmaf(w0, b0.w, ab0);
            }
            if (m21 <= cut2) {
                float w1 = __expf(-0.5f * m21);
                ar1 = fmaf(w1, b1.y, ar1);
                ag1 = fmaf(w1, b1.z, ag1);
                ab1 = fmaf(w1, b1.w, ab1);
            }
        }
        if (j < total) {
            float4 a0 = s0[j], b0 = s1[j];
            float dx0 = x - a0.x, dy0 = y - a0.y;
            float m20 = a0.z * dx0 * dx0;
            m20 = fmaf(a0.w * dx0, dy0, m20);
            m20 = fmaf(b0.x * dy0, dy0, m20);
            if (m20 <= cut2) {
                float w0 = __expf(-0.5f * m20);
                ar0 = fmaf(w0, b0.y, ar0);
                ag0 = fmaf(w0, b0.z, ag0);
                ab0 = fmaf(w0, b0.w, ab0);
            }
        }
    }

    if (px < W && py < H) {
        int o = (py * W + px) * 3;
        out[o + 0] = ar0 + ar1;
        out[o + 1] = ag0 + ag1;
        out[o + 2] = ab0 + ab1;
    }
}

extern "C" void kernel_launch(void* const* d_in, const int* in_sizes, int n_in,
                              void* d_out, int out_size) {
    const float* opacity = (const float*)d_in[0];
    const float* means   = (const float*)d_in[1];
    const float* stds    = (const float*)d_in[2];
    const float* rhos    = (const float*)d_in[3];
    const float* colors  = (const float*)d_in[4];
    const int*   scale_p = (const int*)d_in[7];
    const int*   ratio_p = (const int*)d_in[8];

    int N = in_sizes[0];
    if (N > MAXN) N = MAXN;

    // Derive H, W host-side from out_size (H*W*3); square raster assumed.
    int hw = out_size / 3;
    int W = (int)lrint(sqrt((double)hw));
    while (W > 1 && (hw % W) != 0) W--;
    int H = hw / W;

    float* out = (float*)d_out;

    gr_prepass<<<(N + 255) / 256, 256>>>(opacity, means, stds, rhos, colors,
                                         scale_p, ratio_p, N);

    dim3 grid((W + TILE_W - 1) / TILE_W, (H + TILE_H - 1) / TILE_H);
    gr_raster<<<grid, NTHREADS>>>(out, N, W, H);
}

// round 3
// speedup vs baseline: 1.1359x; 1.1189x over previous
#include <cuda_runtime.h>
#include <math.h>

// ---------------------------------------------------------------------------
// GaussianRasterizer — single-kernel tile splatting, split-N within the CTA.
// CTA = 256 threads. Warps 0-3 (half 0) and warps 4-7 (half 1) both own the
// same 16x8 pixel tile but process disjoint halves of the Gaussian list,
// each with its own cull/compact/eval pipeline synchronized by named
// barriers. Partials combine deterministically through smem at the end.
// ---------------------------------------------------------------------------

#define TILE_W 16
#define TILE_H 8
#define NT 256
#define HALF 128
#define CPT 4
#define CHUNK 512   // candidates per chunk per half (= HALF * CPT)

// Scalars may arrive as int32 or float32 bits; small ints are unambiguous.
__device__ __forceinline__ float scalar_as_float(const int* p) {
    int v = *p;
    if (v >= 0 && v <= 1000000) return (float)v;
    return __int_as_float(v);
}

__device__ __forceinline__ void bar_half(int id) {
    asm volatile("bar.sync %0, %1;" :: "r"(id), "n"(HALF) : "memory");
}

__global__ __launch_bounds__(NT)
void gr_raster(const float* __restrict__ opacity,
               const float* __restrict__ means,
               const float* __restrict__ stds,
               const float* __restrict__ rhos,
               const float* __restrict__ colors,
               const int*   __restrict__ scale_p,
               const int*   __restrict__ ratio_p,
               float* __restrict__ out, int N, int W, int H) {
    // Survivor SoA per half: s0 = {mx, my, hia, hib2}, s1 = {hic, cr, cg, cb}
    // where hia/hib2/hic have -0.5 folded in (expf arg is direct).
    __shared__ float4 s0[2][CHUNK];
    __shared__ float4 s1[2][CHUNK];
    __shared__ int    swc[2][4];
    __shared__ float  sacc[HALF][3];

    const int tid  = threadIdx.x;
    const int half = tid >> 7;          // 0 or 1
    const int htid = tid & (HALF - 1);
    const int lane = tid & 31;
    const int hwid = (tid >> 5) & 3;    // warp index within half
    const int barid = half + 1;

    const int px = blockIdx.x * TILE_W + (htid & (TILE_W - 1));
    const int py = blockIdx.y * TILE_H + (htid / TILE_W);
    const float x = (float)px + 0.5f;
    const float y = (float)py + 0.5f;

    // Tile center / half-extent in pixel-center coords.
    const float tcx = (float)(blockIdx.x * TILE_W) + 0.5f + (TILE_W - 1) * 0.5f;
    const float tcy = (float)(blockIdx.y * TILE_H) + 0.5f + (TILE_H - 1) * 0.5f;
    const float thx = (TILE_W - 1) * 0.5f;
    const float thy = (TILE_H - 1) * 0.5f;

    const float s   = scalar_as_float(scale_p);
    const float r   = scalar_as_float(ratio_p);
    const float rs  = r * s;
    const float cth = -0.5f * r * r;    // eval passes when m2' >= cth

    const float2* __restrict__ mean2 = (const float2*)means;
    const float2* __restrict__ std2  = (const float2*)stds;

    // This half's candidate range.
    const int N0  = (N + 1) >> 1;
    const int beg = half ? N0 : 0;
    const int end = half ? N  : N0;

    float ar0 = 0.f, ag0 = 0.f, ab0 = 0.f;
    float ar1 = 0.f, ag1 = 0.f, ab1 = 0.f;

    for (int base = beg; base < end; base += CHUNK) {
        // ---- Cull: 4 contiguous candidates per thread (batched LDG.64s).
        const int ib = base + htid * CPT;
        float2 mk[CPT], sk[CPT];
        unsigned hm = 0;
        int cnt = 0;
        #pragma unroll
        for (int k = 0; k < CPT; k++) {
            int i = ib + k;
            if (i < end) {
                mk[k] = mean2[i];
                sk[k] = std2[i];
                // |mx - tcx| <= thx + r*sx  (exact cull; sx = stds.x * s)
                bool hit = (fabsf(mk[k].x - tcx) <= fmaf(rs, sk[k].x, thx)) &
                           (fabsf(mk[k].y - tcy) <= fmaf(rs, sk[k].y, thy));
                if (hit) { hm |= (1u << k); cnt++; }
            }
        }

        // ---- Deterministic scan over this half's 128 threads.
        int incl = cnt;
        #pragma unroll
        for (int d = 1; d < 32; d <<= 1) {
            int v = __shfl_up_sync(0xffffffffu, incl, d);
            if (lane >= d) incl += v;
        }
        if (lane == 31) swc[half][hwid] = incl;
        bar_half(barid);                       // swc ready; prev eval done

        int off = 0, total = 0;
        #pragma unroll
        for (int w = 0; w < 4; w++) {
            int c = swc[half][w];
            if (w < hwid) off += c;
            total += c;
        }
        int slot = off + (incl - cnt);

        // ---- Compaction: compute inverse covariance only for survivors.
        #pragma unroll
        for (int k = 0; k < CPT; k++) {
            if ((hm >> k) & 1u) {
                int i = ib + k;
                float sx  = sk[k].x * s;
                float sy  = sk[k].y * s;
                float rho = rhos[i];
                float om  = 1.0f - rho * rho;
                float hia  = __fdividef(-0.5f, sx * sx * om);
                float hic  = __fdividef(-0.5f, sy * sy * om);
                float hib2 = __fdividef(rho,   sx * sy * om);
                float o = opacity[i];
                s0[half][slot] = make_float4(mk[k].x, mk[k].y, hia, hib2);
                s1[half][slot] = make_float4(hic,
                                             o * colors[3 * i + 0],
                                             o * colors[3 * i + 1],
                                             o * colors[3 * i + 2]);
                slot++;
            }
        }
        bar_half(barid);                       // survivor list ready

        // ---- Eval: 2-way unrolled, dual accumulator chains.
        int j = 0;
        for (; j + 1 < total; j += 2) {
            float4 a0 = s0[half][j],     b0 = s1[half][j];
            float4 a1 = s0[half][j + 1], b1 = s1[half][j + 1];

            float dx0 = x - a0.x, dy0 = y - a0.y;
            float m0  = a0.z * dx0 * dx0;
            m0 = fmaf(a0.w * dx0, dy0, m0);
            m0 = fmaf(b0.x * dy0, dy0, m0);

            float dx1 = x - a1.x, dy1 = y - a1.y;
            float m1  = a1.z * dx1 * dx1;
            m1 = fmaf(a1.w * dx1, dy1, m1);
            m1 = fmaf(b1.x * dy1, dy1, m1);

            if (m0 >= cth) {
                float w0 = __expf(m0);
                ar0 = fmaf(w0, b0.y, ar0);
                ag0 = fmaf(w0, b0.z, ag0);
                ab0 = fmaf(w0, b0.w, ab0);
            }
            if (m1 >= cth) {
                float w1 = __expf(m1);
                ar1 = fmaf(w1, b1.y, ar1);
                ag1 = fmaf(w1, b1.z, ag1);
                ab1 = fmaf(w1, b1.w, ab1);
            }
        }
        if (j < total) {
            float4 a0 = s0[half][j], b0 = s1[half][j];
            float dx0 = x - a0.x, dy0 = y - a0.y;
            float m0  = a0.z * dx0 * dx0;
            m0 = fmaf(a0.w * dx0, dy0, m0);
            m0 = fmaf(b0.x * dy0, dy0, m0);
            if (m0 >= cth) {
                float w0 = __expf(m0);
                ar0 = fmaf(w0, b0.y, ar0);
                ag0 = fmaf(w0, b0.z, ag0);
                ab0 = fmaf(w0, b0.w, ab0);
            }
        }
    }

    // ---- Combine halves deterministically (half0 + half1), write out.
    if (half) {
        sacc[htid][0] = ar0 + ar1;
        sacc[htid][1] = ag0 + ag1;
        sacc[htid][2] = ab0 + ab1;
    }
    __syncthreads();
    if (!half && px < W && py < H) {
        int o = (py * W + px) * 3;
        out[o + 0] = (ar0 + ar1) + sacc[htid][0];
        out[o + 1] = (ag0 + ag1) + sacc[htid][1];
        out[o + 2] = (ab0 + ab1) + sacc[htid][2];
    }
}

extern "C" void kernel_launch(void* const* d_in, const int* in_sizes, int n_in,
                              void* d_out, int out_size) {
    const float* opacity = (const float*)d_in[0];
    const float* means   = (const float*)d_in[1];
    const float* stds    = (const float*)d_in[2];
    const float* rhos    = (const float*)d_in[3];
    const float* colors  = (const float*)d_in[4];
    const int*   scale_p = (const int*)d_in[7];
    const int*   ratio_p = (const int*)d_in[8];

    int N = in_sizes[0];

    // Derive H, W host-side from out_size (H*W*3); square raster assumed.
    int hw = out_size / 3;
    int W = (int)lrint(sqrt((double)hw));
    while (W > 1 && (hw % W) != 0) W--;
    int H = hw / W;

    float* out = (float*)d_out;

    dim3 grid((W + TILE_W - 1) / TILE_W, (H + TILE_H - 1) / TILE_H);
    gr_raster<<<grid, NT>>>(opacity, means, stds, rhos, colors,
                            scale_p, ratio_p, out, N, W, H);
}

// round 4
// speedup vs baseline: 1.1555x; 1.0173x over previous
#include <cuda_runtime.h>
#include <math.h>

// ---------------------------------------------------------------------------
// GaussianRasterizer — single-kernel tile splatting, split-N within the CTA.
// CTA = 256 threads. Warps 0-3 (half 0) and warps 4-7 (half 1) both own the
// same 16x8 pixel tile but process disjoint halves of the Gaussian list.
// Branch-free eval loop (FSEL-zeroed exp weights).
// ---------------------------------------------------------------------------

#define TILE_W 16
#define TILE_H 8
#define NT 256
#define HALF 128
#define CPT 4
#define CHUNK 512   // candidates per chunk per half (= HALF * CPT)

__device__ __forceinline__ float scalar_as_float(const int* p) {
    int v = *p;
    if (v >= 0 && v <= 1000000) return (float)v;
    return __int_as_float(v);
}

__device__ __forceinline__ void bar_half(int id) {
    asm volatile("bar.sync %0, %1;" :: "r"(id), "n"(HALF) : "memory");
}

__global__ __launch_bounds__(NT, 5)
void gr_raster(const float* __restrict__ opacity,
               const float* __restrict__ means,
               const float* __restrict__ stds,
               const float* __restrict__ rhos,
               const float* __restrict__ colors,
               const int*   __restrict__ scale_p,
               const int*   __restrict__ ratio_p,
               float* __restrict__ out, int N, int W, int H) {
    // Survivor SoA per half: s0 = {mx, my, hia, hib2}, s1 = {hic, cr, cg, cb}
    // (-0.5 folded into hia/hib2/hic so __expf argument is direct).
    __shared__ float4 s0[2][CHUNK];
    __shared__ float4 s1[2][CHUNK];
    __shared__ int    swc[2][4];
    __shared__ float  sacc[HALF][3];

    const int tid  = threadIdx.x;
    const int half = tid >> 7;
    const int htid = tid & (HALF - 1);
    const int lane = tid & 31;
    const int hwid = (tid >> 5) & 3;
    const int barid = half + 1;

    const int px = blockIdx.x * TILE_W + (htid & (TILE_W - 1));
    const int py = blockIdx.y * TILE_H + (htid / TILE_W);
    const float x = (float)px + 0.5f;
    const float y = (float)py + 0.5f;

    const float tcx = (float)(blockIdx.x * TILE_W) + 0.5f + (TILE_W - 1) * 0.5f;
    const float tcy = (float)(blockIdx.y * TILE_H) + 0.5f + (TILE_H - 1) * 0.5f;
    const float thx = (TILE_W - 1) * 0.5f;
    const float thy = (TILE_H - 1) * 0.5f;

    const float s   = scalar_as_float(scale_p);
    const float r   = scalar_as_float(ratio_p);
    const float rs  = r * s;
    const float cth = -0.5f * r * r;    // pass when folded m2 >= cth

    const float2* __restrict__ mean2 = (const float2*)means;
    const float2* __restrict__ std2  = (const float2*)stds;

    const int N0  = (N + 1) >> 1;
    const int beg = half ? N0 : 0;
    const int end = half ? N  : N0;

    float ar0 = 0.f, ag0 = 0.f, ab0 = 0.f;
    float ar1 = 0.f, ag1 = 0.f, ab1 = 0.f;

    for (int base = beg; base < end; base += CHUNK) {
        // ---- Cull: 4 contiguous candidates per thread.
        const int ib = base + htid * CPT;
        float2 mk[CPT], sk[CPT];
        unsigned hm = 0;
        int cnt = 0;
        #pragma unroll
        for (int k = 0; k < CPT; k++) {
            int i = ib + k;
            if (i < end) {
                mk[k] = mean2[i];
                sk[k] = std2[i];
                bool hit = (fabsf(mk[k].x - tcx) <= fmaf(rs, sk[k].x, thx)) &
                           (fabsf(mk[k].y - tcy) <= fmaf(rs, sk[k].y, thy));
                if (hit) { hm |= (1u << k); cnt++; }
            }
        }

        // ---- Deterministic scan over this half's 128 threads.
        int incl = cnt;
        #pragma unroll
        for (int d = 1; d < 32; d <<= 1) {
            int v = __shfl_up_sync(0xffffffffu, incl, d);
            if (lane >= d) incl += v;
        }
        if (lane == 31) swc[half][hwid] = incl;
        bar_half(barid);                       // swc ready; prev eval done

        int off = 0, total = 0;
        #pragma unroll
        for (int w = 0; w < 4; w++) {
            int c = swc[half][w];
            if (w < hwid) off += c;
            total += c;
        }
        int slot = off + (incl - cnt);

        // ---- Compaction: inv-cov only for survivors.
        #pragma unroll
        for (int k = 0; k < CPT; k++) {
            if ((hm >> k) & 1u) {
                int i = ib + k;
                float rho = rhos[i];
                float o   = opacity[i];
                float c0  = colors[3 * i + 0];
                float c1  = colors[3 * i + 1];
                float c2  = colors[3 * i + 2];
                float sx  = sk[k].x * s;
                float sy  = sk[k].y * s;
                float om  = 1.0f - rho * rho;
                float hia  = __fdividef(-0.5f, sx * sx * om);
                float hic  = __fdividef(-0.5f, sy * sy * om);
                float hib2 = __fdividef(rho,   sx * sy * om);
                s0[half][slot] = make_float4(mk[k].x, mk[k].y, hia, hib2);
                s1[half][slot] = make_float4(hic, o * c0, o * c1, o * c2);
                slot++;
            }
        }
        bar_half(barid);                       // survivor list ready

        // ---- Eval: branch-free, 2-way unrolled, dual accumulators.
        int j = 0;
        for (; j + 1 < total; j += 2) {
            float4 a0 = s0[half][j],     b0 = s1[half][j];
            float4 a1 = s0[half][j + 1], b1 = s1[half][j + 1];

            float dx0 = x - a0.x, dy0 = y - a0.y;
            float m0  = a0.z * dx0 * dx0;
            m0 = fmaf(a0.w * dx0, dy0, m0);
            m0 = fmaf(b0.x * dy0, dy0, m0);

            float dx1 = x - a1.x, dy1 = y - a1.y;
            float m1  = a1.z * dx1 * dx1;
            m1 = fmaf(a1.w * dx1, dy1, m1);
            m1 = fmaf(b1.x * dy1, dy1, m1);

            float w0 = __expf(m0);
            float w1 = __expf(m1);
            w0 = (m0 >= cth) ? w0 : 0.0f;
            w1 = (m1 >= cth) ? w1 : 0.0f;

            ar0 = fmaf(w0, b0.y, ar0);
            ag0 = fmaf(w0, b0.z, ag0);
            ab0 = fmaf(w0, b0.w, ab0);
            ar1 = fmaf(w1, b1.y, ar1);
            ag1 = fmaf(w1, b1.z, ag1);
            ab1 = fmaf(w1, b1.w, ab1);
        }
        if (j < total) {
            float4 a0 = s0[half][j], b0 = s1[half][j];
            float dx0 = x - a0.x, dy0 = y - a0.y;
            float m0  = a0.z * dx0 * dx0;
            m0 = fmaf(a0.w * dx0, dy0, m0);
            m0 = fmaf(b0.x * dy0, dy0, m0);
            float w0 = __expf(m0);
            w0 = (m0 >= cth) ? w0 : 0.0f;
            ar0 = fmaf(w0, b0.y, ar0);
            ag0 = fmaf(w0, b0.z, ag0);
            ab0 = fmaf(w0, b0.w, ab0);
        }
    }

    // ---- Combine halves deterministically (half0 + half1), write out.
    if (half) {
        sacc[htid][0] = ar0 + ar1;
        sacc[htid][1] = ag0 + ag1;
        sacc[htid][2] = ab0 + ab1;
    }
    __syncthreads();
    if (!half && px < W && py < H) {
        int o = (py * W + px) * 3;
        out[o + 0] = (ar0 + ar1) + sacc[htid][0];
        out[o + 1] = (ag0 + ag1) + sacc[htid][1];
        out[o + 2] = (ab0 + ab1) + sacc[htid][2];
    }
}

extern "C" void kernel_launch(void* const* d_in, const int* in_sizes, int n_in,
                              void* d_out, int out_size) {
    const float* opacity = (const float*)d_in[0];
    const float* means   = (const float*)d_in[1];
    const float* stds    = (const float*)d_in[2];
    const float* rhos    = (const float*)d_in[3];
    const float* colors  = (const float*)d_in[4];
    const int*   scale_p = (const int*)d_in[7];
    const int*   ratio_p = (const int*)d_in[8];

    int N = in_sizes[0];

    int hw = out_size / 3;
    int W = (int)lrint(sqrt((double)hw));
    while (W > 1 && (hw % W) != 0) W--;
    int H = hw / W;

    float* out = (float*)d_out;

    dim3 grid((W + TILE_W - 1) / TILE_W, (H + TILE_H - 1) / TILE_H);
    gr_raster<<<grid, NT>>>(opacity, means, stds, rhos, colors,
                            scale_p, ratio_p, out, N, W, H);
}